// round 15
// baseline (speedup 1.0000x reference)
#include <cuda_runtime.h>
#include <cstddef>
#include <cstdint>

#define LAYERS 5
#define H 128
#define T 2048
#define BATCH 256
#define G 29            // batch groups per layer (grid = 145)
#define BG 9            // rows per group
#define BPAD 264        // padded batch rows in staging buffer
#define NTH 512
#define KS 8            // slots (2 warps per slot)
#define PUB 8           // flag publish granularity

#define NBUF_A 3
#define NBUF_B 2
#define ACH_K 8                          // k-rows per A chunk
#define ACH_PER_STEP 16
#define A_MAT_BYTES (ACH_K * H * 4)      // 4096
#define A_CHUNK_BYTES (5 * A_MAT_BYTES)  // 20480
#define BCH_K 16                         // k-rows per B chunk
#define BCH_PER_STEP 8
#define B_CHUNK_BYTES (BCH_K * H * 4)    // 8192

typedef unsigned long long ull;

__device__ float Xbuf[(size_t)(LAYERS - 1) * T * BPAD * H];
__device__ int progressFlag[LAYERS * G];

__device__ __forceinline__ ull pack2(float lo, float hi) {
    ull r; asm("mov.b64 %0,{%1,%2};" : "=l"(r) : "f"(lo), "f"(hi)); return r;
}
__device__ __forceinline__ void fma2(ull& acc, ull a, ull b) {
    asm("fma.rn.f32x2 %0,%1,%2,%0;" : "+l"(acc) : "l"(a), "l"(b));
}
__device__ __forceinline__ float lo_of(ull v) {
    return __uint_as_float((unsigned)(v & 0xffffffffull));
}
__device__ __forceinline__ float fast_sigmoid(float x) {
    return 1.0f / (1.0f + __expf(-x));
}
__device__ __forceinline__ int ld_acquire(const int* p) {
    int v; asm volatile("ld.acquire.gpu.s32 %0,[%1];" : "=r"(v) : "l"(p) : "memory"); return v;
}
__device__ __forceinline__ void st_release(int* p, int v) {
    asm volatile("st.release.gpu.s32 [%0],%1;" :: "l"(p), "r"(v) : "memory");
}
__device__ __forceinline__ uint32_t smem_u32(const void* p) {
    uint32_t a;
    asm("{ .reg .u64 t; cvta.to.shared.u64 t, %1; cvt.u32.u64 %0, t; }" : "=r"(a) : "l"(p));
    return a;
}
#define MBAR_INIT(a, n) \
    asm volatile("mbarrier.init.shared.b64 [%0], %1;" :: "r"(a), "r"(n) : "memory")
#define MBAR_EXPECT_TX(a, bytes) \
    asm volatile("mbarrier.arrive.expect_tx.shared.b64 _, [%0], %1;" :: "r"(a), "r"(bytes) : "memory")
#define MBAR_ARRIVE(a) \
    asm volatile("mbarrier.arrive.shared.b64 _, [%0];" :: "r"(a) : "memory")
#define TMA_BULK(dst, src, bytes, mbar) \
    asm volatile("cp.async.bulk.shared::cta.global.mbarrier::complete_tx::bytes [%0], [%1], %2, [%3];" \
                 :: "r"(dst), "l"(src), "r"(bytes), "r"(mbar) : "memory")

__device__ __forceinline__ void mbar_wait(uint32_t mbar, uint32_t parity) {
    uint32_t done;
    asm volatile(
        "{\n\t.reg .pred p;\n\t"
        "mbarrier.try_wait.parity.acquire.cta.shared::cta.b64 p, [%1], %2;\n\t"
        "selp.b32 %0, 1, 0, p;\n\t}"
        : "=r"(done) : "r"(mbar), "r"(parity) : "memory");
    if (!done) {
        asm volatile(
            "{\n\t.reg .pred P1;\n\t"
            "W%=:\n\t"
            "mbarrier.try_wait.parity.acquire.cta.shared::cta.b64 P1, [%0], %1, 0x989680;\n\t"
            "@P1 bra.uni D%=;\n\t"
            "bra.uni W%=;\n\t"
            "D%=:\n\t}"
            :: "r"(mbar), "r"(parity) : "memory");
    }
}

struct Smem {
    float wbufA[NBUF_A][5][ACH_K][H];   //  61440 B
    float wbufB[NBUF_B][BCH_K][H];      //  16384 B
    float partA[KS][3][BG][H];          // 110592 B (partB aliases this)
    ulonglong2 hx[BG][H];               //  18432 B  {h,h | x,x}
    ull   rh2[BG][H];                   //   9216 B
    float zbuf[BG][H];                  //   4608 B
    float preh[BG][H];                  //   4608 B
    float br[H]; float bz[H]; float bh_[H];  // 1536 B
    ull mbarAfP[ACH_PER_STEP];          // per-position full barriers (1 phase/step)
    ull mbarAe[NBUF_A];                 // empty: 16 arrivals (one per warp)
    ull mbarBfP[BCH_PER_STEP];
    ull mbarBe[NBUF_B];
    int avail_sh;
};
static_assert(sizeof(Smem) <= 232448, "smem over limit");

__global__ void reset_kernel() {
    int i = threadIdx.x;
    if (i < LAYERS * G) progressFlag[i] = 0;
}

__global__ __launch_bounds__(NTH, 1)
void gru_layer_kernel(
    const float* __restrict__ inp,
    const float* __restrict__ W_hr, const float* __restrict__ W_xr, const float* __restrict__ b_r,
    const float* __restrict__ W_hz, const float* __restrict__ W_xz, const float* __restrict__ b_z,
    const float* __restrict__ W_hh, const float* __restrict__ W_xh, const float* __restrict__ b_h,
    float* __restrict__ out)
{
    extern __shared__ char smem_raw[];
    Smem& sm = *reinterpret_cast<Smem*>(smem_raw);
    float* partB = &sm.partA[0][0][0][0];      // [KS][BG][H] alias, disjoint lifetime

    const int bid  = blockIdx.x;
    const int l    = bid / G;
    const int g    = bid % G;
    const int row0 = g * BG;
    const int tid  = threadIdx.x;
    const int lane = tid & 31;
    const int jp   = tid & 63;
    const int j0   = jp << 1;
    const int slot = tid >> 6;                 // 0..7

    const float* wA0 = W_hr + l * H * H;
    const float* wA1 = W_xr + l * H * H;
    const float* wA2 = W_hz + l * H * H;
    const float* wA3 = W_xz + l * H * H;
    const float* wA4 = W_xh + l * H * H;
    const float* whh = W_hh + l * H * H;

    for (int i = tid; i < BG * H; i += NTH) {
        reinterpret_cast<ulonglong2*>(&sm.hx[0][0])[i] = make_ulonglong2(0ull, 0ull);
        (&sm.rh2[0][0])[i] = 0ull;
    }
    for (int i = tid; i < H; i += NTH) {
        sm.br[i]  = b_r[l * H + i];
        sm.bz[i]  = b_z[l * H + i];
        sm.bh_[i] = b_h[l * H + i];
    }
    uint32_t AfP[ACH_PER_STEP], Ae[NBUF_A], BfP[BCH_PER_STEP], Be[NBUF_B];
    #pragma unroll
    for (int i = 0; i < ACH_PER_STEP; ++i) AfP[i] = smem_u32(&sm.mbarAfP[i]);
    #pragma unroll
    for (int i = 0; i < NBUF_A; ++i)       Ae[i]  = smem_u32(&sm.mbarAe[i]);
    #pragma unroll
    for (int i = 0; i < BCH_PER_STEP; ++i) BfP[i] = smem_u32(&sm.mbarBfP[i]);
    #pragma unroll
    for (int i = 0; i < NBUF_B; ++i)       Be[i]  = smem_u32(&sm.mbarBe[i]);
    if (tid == 0) {
        #pragma unroll
        for (int i = 0; i < ACH_PER_STEP; ++i) MBAR_INIT(AfP[i], 1);
        #pragma unroll
        for (int i = 0; i < NBUF_A; ++i)       MBAR_INIT(Ae[i], 16);
        #pragma unroll
        for (int i = 0; i < BCH_PER_STEP; ++i) MBAR_INIT(BfP[i], 1);
        #pragma unroll
        for (int i = 0; i < NBUF_B; ++i)       MBAR_INIT(Be[i], 16);
    }
    __syncthreads();

    const uint32_t wA_a = smem_u32(&sm.wbufA[0][0][0][0]);
    const uint32_t wB_a = smem_u32(&sm.wbufB[0][0][0]);

    int nextA = NBUF_A, nextB = NBUF_B;
    if (tid == 0) {
        #pragma unroll
        for (int m = 0; m < NBUF_A; ++m) {
            MBAR_EXPECT_TX(AfP[m], A_CHUNK_BYTES);
            const uint32_t d = wA_a + m * A_CHUNK_BYTES;
            TMA_BULK(d,                   wA0 + m * ACH_K * H, A_MAT_BYTES, AfP[m]);
            TMA_BULK(d + 1 * A_MAT_BYTES, wA1 + m * ACH_K * H, A_MAT_BYTES, AfP[m]);
            TMA_BULK(d + 2 * A_MAT_BYTES, wA2 + m * ACH_K * H, A_MAT_BYTES, AfP[m]);
            TMA_BULK(d + 3 * A_MAT_BYTES, wA3 + m * ACH_K * H, A_MAT_BYTES, AfP[m]);
            TMA_BULK(d + 4 * A_MAT_BYTES, wA4 + m * ACH_K * H, A_MAT_BYTES, AfP[m]);
        }
        #pragma unroll
        for (int m = 0; m < NBUF_B; ++m) {
            MBAR_EXPECT_TX(BfP[m], B_CHUNK_BYTES);
            TMA_BULK(wB_a + m * B_CHUNK_BYTES, whh + m * BCH_K * H, B_CHUNK_BYTES, BfP[m]);
        }
    }

    int avail = (l == 0) ? T : 0;
    const float* xsrc = (l == 0) ? nullptr : &Xbuf[(size_t)(l - 1) * T * BPAD * H];
    float* ysnk = (l == LAYERS - 1) ? nullptr : &Xbuf[(size_t)l * T * BPAD * H];
    int* myflag  = &progressFlag[l * G + g];
    int* srcflag = (l == 0) ? nullptr : &progressFlag[(l - 1) * G + g];

    for (int t = 0; t < T; ++t) {
        if (l > 0 && avail < t + 1) {
            if (tid == 0) {
                int v = ld_acquire(srcflag);
                while (v < t + 1) { __nanosleep(200); v = ld_acquire(srcflag); }
                sm.avail_sh = v;
            }
            __syncthreads();
            avail = sm.avail_sh;
        }

        for (int i = tid; i < BG * H; i += NTH) {
            const int b = i >> 7, k = i & 127;
            const int r = row0 + b;
            float v;
            if (l == 0) {
                v = (r < BATCH) ? inp[((size_t)r * T + t) * H + k] : 0.0f;
            } else {
                v = xsrc[((size_t)t * BPAD + r) * H + k];
            }
            sm.hx[b][k].y = pack2(v, v);
        }
        __syncthreads();

        if (l < LAYERS - 1 && tid == 0 && t > 0 && (t & (PUB - 1)) == 0) {
            __threadfence();
            st_release(myflag, t);
        }

        // ======== Stage A: all warps walk all 16 chunks; slot = k-row in chunk ========
        {
            ull ar[BG], az[BG], ax[BG];
            #pragma unroll
            for (int b = 0; b < BG; ++b) { ar[b] = 0ull; az[b] = 0ull; ax[b] = 0ull; }

            #pragma unroll 1
            for (int c = 0; c < ACH_PER_STEP; ++c) {
                const int gA  = ACH_PER_STEP * t + c;
                const int buf = gA % NBUF_A;
                mbar_wait(AfP[c], (uint32_t)(t & 1));

                const int k = ACH_K * c + slot;          // my k-row this chunk
                const ull w1 = *reinterpret_cast<const ull*>(&sm.wbufA[buf][0][slot][j0]);
                const ull w2 = *reinterpret_cast<const ull*>(&sm.wbufA[buf][1][slot][j0]);
                const ull w3 = *reinterpret_cast<const ull*>(&sm.wbufA[buf][2][slot][j0]);
                const ull w4 = *reinterpret_cast<const ull*>(&sm.wbufA[buf][3][slot][j0]);
                const ull w5 = *reinterpret_cast<const ull*>(&sm.wbufA[buf][4][slot][j0]);
                #pragma unroll
                for (int b = 0; b < BG; ++b) {
                    const ulonglong2 hxv = sm.hx[b][k];  // broadcast LDS.128
                    fma2(ar[b], w1, hxv.x);
                    fma2(ar[b], w2, hxv.y);
                    fma2(az[b], w3, hxv.x);
                    fma2(az[b], w4, hxv.y);
                    fma2(ax[b], w5, hxv.y);
                }
                __syncwarp();
                if (lane == 0) MBAR_ARRIVE(Ae[buf]);

                // tid0 pump: issue chunk gA+3 (same buffer) once all warps release gA
                if (tid == 0) {
                    const int lastA = ACH_PER_STEP * T - 1;
                    int hi = gA + NBUF_A;
                    if (hi > lastA) hi = lastA;
                    for (; nextA <= hi; ++nextA) {
                        const int bufn = nextA % NBUF_A;
                        const int posn = nextA % ACH_PER_STEP;
                        mbar_wait(Ae[bufn], (uint32_t)(((nextA / NBUF_A) - 1) & 1));
                        MBAR_EXPECT_TX(AfP[posn], A_CHUNK_BYTES);
                        const uint32_t d = wA_a + bufn * A_CHUNK_BYTES;
                        TMA_BULK(d,                   wA0 + posn * ACH_K * H, A_MAT_BYTES, AfP[posn]);
                        TMA_BULK(d + 1 * A_MAT_BYTES, wA1 + posn * ACH_K * H, A_MAT_BYTES, AfP[posn]);
                        TMA_BULK(d + 2 * A_MAT_BYTES, wA2 + posn * ACH_K * H, A_MAT_BYTES, AfP[posn]);
                        TMA_BULK(d + 3 * A_MAT_BYTES, wA3 + posn * ACH_K * H, A_MAT_BYTES, AfP[posn]);
                        TMA_BULK(d + 4 * A_MAT_BYTES, wA4 + posn * ACH_K * H, A_MAT_BYTES, AfP[posn]);
                    }
                }
            }
            #pragma unroll
            for (int b = 0; b < BG; ++b) {
                *reinterpret_cast<ull*>(&sm.partA[slot][0][b][j0]) = ar[b];
                *reinterpret_cast<ull*>(&sm.partA[slot][1][b][j0]) = az[b];
                *reinterpret_cast<ull*>(&sm.partA[slot][2][b][j0]) = ax[b];
            }
        }
        __syncthreads();

        // ---- Combine A ----
        for (int i = tid; i < 3 * BG * H; i += NTH) {
            const int g3 = i / (BG * H);
            const int r  = i % (BG * H);
            const int b  = r >> 7;
            const int j  = r & 127;
            float ssum = 0.f;
            #pragma unroll
            for (int ss = 0; ss < KS; ++ss) ssum += sm.partA[ss][g3][b][j];
            if (g3 == 0) {
                const float R  = fast_sigmoid(ssum + sm.br[j]);
                const float rv = R * lo_of(sm.hx[b][j].x);
                sm.rh2[b][j] = pack2(rv, rv);
            } else if (g3 == 1) {
                sm.zbuf[b][j] = fast_sigmoid(ssum + sm.bz[j]);
            } else {
                sm.preh[b][j] = ssum + sm.bh_[j];
            }
        }
        __syncthreads();

        // ======== Stage B: all warps walk all 8 chunks; slot = 2 k-rows ========
        {
            ull bh[BG];
            #pragma unroll
            for (int b = 0; b < BG; ++b) bh[b] = 0ull;

            #pragma unroll 1
            for (int c = 0; c < BCH_PER_STEP; ++c) {
                const int gB  = BCH_PER_STEP * t + c;
                const int buf = gB % NBUF_B;
                mbar_wait(BfP[c], (uint32_t)(t & 1));

                const int k0 = BCH_K * c + slot;
                const int k1 = k0 + 8;
                const ull wa = *reinterpret_cast<const ull*>(&sm.wbufB[buf][slot][j0]);
                const ull wb = *reinterpret_cast<const ull*>(&sm.wbufB[buf][slot + 8][j0]);
                #pragma unroll
                for (int b = 0; b < BG; ++b) {
                    fma2(bh[b], wa, sm.rh2[b][k0]);
                    fma2(bh[b], wb, sm.rh2[b][k1]);
                }
                __syncwarp();
                if (lane == 0) MBAR_ARRIVE(Be[buf]);

                if (tid == 0) {
                    const int lastB = BCH_PER_STEP * T - 1;
                    int hi = gB + NBUF_B;
                    if (hi > lastB) hi = lastB;
                    for (; nextB <= hi; ++nextB) {
                        const int bufn = nextB % NBUF_B;
                        const int posn = nextB % BCH_PER_STEP;
                        mbar_wait(Be[bufn], (uint32_t)(((nextB / NBUF_B) - 1) & 1));
                        MBAR_EXPECT_TX(BfP[posn], B_CHUNK_BYTES);
                        TMA_BULK(wB_a + bufn * B_CHUNK_BYTES, whh + posn * BCH_K * H,
                                 B_CHUNK_BYTES, BfP[posn]);
                    }
                }
            }
            #pragma unroll
            for (int b = 0; b < BG; ++b)
                *reinterpret_cast<ull*>(&partB[((slot * BG + b) << 7) + j0]) = bh[b];
        }
        __syncthreads();

        // ---- Combine B ----
        for (int i = tid; i < BG * H; i += NTH) {
            const int b = i >> 7;
            const int j = i & 127;
            float ssum = 0.f;
            #pragma unroll
            for (int ss = 0; ss < KS; ++ss) ssum += partB[((ss * BG + b) << 7) + j];
            const float htld = tanhf(ssum + sm.preh[b][j]);
            const float Z    = sm.zbuf[b][j];
            const float hv   = lo_of(sm.hx[b][j].x);
            const float hn   = Z * htld + (1.0f - Z) * hv;
            sm.hx[b][j].x = pack2(hn, hn);
            const int row = row0 + b;
            if (l == LAYERS - 1) {
                if (row < BATCH)
                    out[((size_t)row * T + t) * H + j] = hn;
            } else {
                ysnk[((size_t)t * BPAD + row) * H + j] = hn;
            }
        }
        __syncthreads();
    }

    if (l < LAYERS - 1 && tid == 0) {
        __threadfence();
        st_release(myflag, T);
    }
}

extern "C" void kernel_launch(void* const* d_in, const int* in_sizes, int n_in,
                              void* d_out, int out_size) {
    (void)in_sizes; (void)n_in; (void)out_size;
    const float* inp  = (const float*)d_in[0];
    const float* W_hr = (const float*)d_in[1];
    const float* W_xr = (const float*)d_in[2];
    const float* b_r  = (const float*)d_in[3];
    const float* W_hz = (const float*)d_in[4];
    const float* W_xz = (const float*)d_in[5];
    const float* b_z  = (const float*)d_in[6];
    const float* W_hh = (const float*)d_in[7];
    const float* W_xh = (const float*)d_in[8];
    const float* b_h  = (const float*)d_in[9];
    float* out = (float*)d_out;

    reset_kernel<<<1, 256>>>();

    cudaFuncSetAttribute(gru_layer_kernel,
                         cudaFuncAttributeMaxDynamicSharedMemorySize,
                         (int)sizeof(Smem));
    gru_layer_kernel<<<LAYERS * G, NTH, sizeof(Smem)>>>(
        inp, W_hr, W_xr, b_r, W_hz, W_xz, b_z, W_hh, W_xh, b_h, out);
}

// round 16
// speedup vs baseline: 2.1519x; 2.1519x over previous
#include <cuda_runtime.h>
#include <cstddef>
#include <cstdint>

#define LAYERS 5
#define H 128
#define T 2048
#define BATCH 256
#define G 29            // batch groups per layer (grid = 145)
#define BG 9            // rows per group
#define BPAD 264        // padded batch rows in staging buffer
#define NTH 512
#define KS 8            // k-slices (one warp-pair per slice)
#define KPER 16         // k rows per slice
#define PUB 8           // flag publish granularity
#define NASUB 8         // A sub-chunks per step (2 k-rows each)
#define NBSUB 2         // B sub-chunks per step (8 k-rows each)

typedef unsigned long long ull;

__device__ float Xbuf[(size_t)(LAYERS - 1) * T * BPAD * H];
__device__ int progressFlag[LAYERS * G];

__device__ __forceinline__ ull pack2(float lo, float hi) {
    ull r; asm("mov.b64 %0,{%1,%2};" : "=l"(r) : "f"(lo), "f"(hi)); return r;
}
__device__ __forceinline__ void fma2(ull& acc, ull a, ull b) {
    asm("fma.rn.f32x2 %0,%1,%2,%0;" : "+l"(acc) : "l"(a), "l"(b));
}
__device__ __forceinline__ float lo_of(ull v) {
    return __uint_as_float((unsigned)(v & 0xffffffffull));
}
__device__ __forceinline__ float fast_sigmoid(float x) {
    return 1.0f / (1.0f + __expf(-x));
}
__device__ __forceinline__ int ld_acquire(const int* p) {
    int v; asm volatile("ld.acquire.gpu.s32 %0,[%1];" : "=r"(v) : "l"(p) : "memory"); return v;
}
__device__ __forceinline__ void st_release(int* p, int v) {
    asm volatile("st.release.gpu.s32 [%0],%1;" :: "l"(p), "r"(v) : "memory");
}
__device__ __forceinline__ uint32_t smem_u32(const void* p) {
    uint32_t a;
    asm("{ .reg .u64 t; cvta.to.shared.u64 t, %1; cvt.u32.u64 %0, t; }" : "=r"(a) : "l"(p));
    return a;
}
__device__ __forceinline__ void cpa8(uint32_t s, const float* g) {
    asm volatile("cp.async.ca.shared.global [%0], [%1], 8;" :: "r"(s), "l"(g) : "memory");
}
#define CP_COMMIT() asm volatile("cp.async.commit_group;" ::: "memory")
#define CP_WAIT1()  asm volatile("cp.async.wait_group 1;" ::: "memory")

struct Smem {
    // Per-thread-private weight staging: [ks][buf2][mat5][kk2][jp64] of ull.
    // Stage B aliases buf slot d with layout [kk8][jp64] (8*64 <= 10*64 cells).
    ull   wbuf[KS][2][5][2][64];      //  81,920 B
    float partA[KS][3][BG][H];        // 110,592 B (partB aliases)
    ulonglong2 hx[BG][H];             //  18,432 B  {h,h | x,x}
    ull   rh2[BG][H];                 //   9,216 B
    float zbuf[BG][H];                //   4,608 B
    float preh[BG][H];                //   4,608 B
    float br[H]; float bz[H]; float bh_[H];  // 1,536 B
    int   avail_sh;
};                                    // 230,916 B
static_assert(sizeof(Smem) <= 232448, "smem over limit");

__global__ void reset_kernel() {
    int i = threadIdx.x;
    if (i < LAYERS * G) progressFlag[i] = 0;
}

__global__ __launch_bounds__(NTH, 1)
void gru_layer_kernel(
    const float* __restrict__ inp,
    const float* __restrict__ W_hr, const float* __restrict__ W_xr, const float* __restrict__ b_r,
    const float* __restrict__ W_hz, const float* __restrict__ W_xz, const float* __restrict__ b_z,
    const float* __restrict__ W_hh, const float* __restrict__ W_xh, const float* __restrict__ b_h,
    float* __restrict__ out)
{
    extern __shared__ char smem_raw[];
    Smem& sm = *reinterpret_cast<Smem*>(smem_raw);
    float* partB = &sm.partA[0][0][0][0];      // [KS][BG][H] alias, disjoint lifetime

    const int bid  = blockIdx.x;
    const int l    = bid / G;
    const int g    = bid % G;
    const int row0 = g * BG;
    const int tid  = threadIdx.x;
    const int jp   = tid & 63;
    const int j0   = jp << 1;
    const int ks   = (tid >> 6) & 7;
    const int k0   = ks * KPER;

    const float* wA0 = W_hr + l * H * H;
    const float* wA1 = W_xr + l * H * H;
    const float* wA2 = W_hz + l * H * H;
    const float* wA3 = W_xz + l * H * H;
    const float* wA4 = W_xh + l * H * H;
    const float* whh = W_hh + l * H * H;

    for (int i = tid; i < BG * H; i += NTH) {
        reinterpret_cast<ulonglong2*>(&sm.hx[0][0])[i] = make_ulonglong2(0ull, 0ull);
        (&sm.rh2[0][0])[i] = 0ull;
    }
    for (int i = tid; i < H; i += NTH) {
        sm.br[i]  = b_r[l * H + i];
        sm.bz[i]  = b_z[l * H + i];
        sm.bh_[i] = b_h[l * H + i];
    }
    __syncthreads();

    // My weight-staging base (cell granularity: ull). Cell (buf,m,kk) at
    // wbuf_s + ((buf*10 + m*2 + kk)*64)*8 ; B-sub d cell kk at ((d*10 + kk)*64)*8.
    const uint32_t wbuf_s = smem_u32(&sm.wbuf[ks][0][0][0][jp]);

    // Issue A sub-chunk c into buf c&1 (10 cp.async of 8B each).
    auto issueA = [&](int c) {
        const int kb = k0 + c * 2;
        const uint32_t base = wbuf_s + (uint32_t)((c & 1) * 10 * 64) * 8u;
        #pragma unroll
        for (int kk = 0; kk < 2; ++kk) {
            const int koff = (kb + kk) * H + j0;
            cpa8(base + (uint32_t)((0 * 2 + kk) * 64) * 8u, wA0 + koff);
            cpa8(base + (uint32_t)((1 * 2 + kk) * 64) * 8u, wA1 + koff);
            cpa8(base + (uint32_t)((2 * 2 + kk) * 64) * 8u, wA2 + koff);
            cpa8(base + (uint32_t)((3 * 2 + kk) * 64) * 8u, wA3 + koff);
            cpa8(base + (uint32_t)((4 * 2 + kk) * 64) * 8u, wA4 + koff);
        }
        CP_COMMIT();
    };
    // Issue B sub-chunk d into slot d (8 cp.async of 8B).
    auto issueB = [&](int d) {
        const int kb = k0 + d * 8;
        const uint32_t base = wbuf_s + (uint32_t)(d * 10 * 64) * 8u;
        #pragma unroll
        for (int kk = 0; kk < 8; ++kk)
            cpa8(base + (uint32_t)(kk * 64) * 8u, whh + (kb + kk) * H + j0);
        CP_COMMIT();
    };

    // Prologue: 2 A-subs in flight.
    issueA(0);
    issueA(1);

    int avail = (l == 0) ? T : 0;
    const float* xsrc = (l == 0) ? nullptr : &Xbuf[(size_t)(l - 1) * T * BPAD * H];
    float* ysnk = (l == LAYERS - 1) ? nullptr : &Xbuf[(size_t)l * T * BPAD * H];
    int* myflag  = &progressFlag[l * G + g];
    int* srcflag = (l == 0) ? nullptr : &progressFlag[(l - 1) * G + g];

    for (int t = 0; t < T; ++t) {
        if (l > 0 && avail < t + 1) {
            if (tid == 0) {
                int v = ld_acquire(srcflag);
                while (v < t + 1) { __nanosleep(200); v = ld_acquire(srcflag); }
                sm.avail_sh = v;
            }
            __syncthreads();
            avail = sm.avail_sh;
        }

        // ---- xload: x_t -> hx .y ----
        for (int i = tid; i < BG * H; i += NTH) {
            const int b = i >> 7, k = i & 127;
            const int r = row0 + b;
            float v;
            if (l == 0) {
                v = (r < BATCH) ? inp[((size_t)r * T + t) * H + k] : 0.0f;
            } else {
                v = xsrc[((size_t)t * BPAD + r) * H + k];
            }
            sm.hx[b][k].y = pack2(v, v);
        }
        __syncthreads();

        if (l < LAYERS - 1 && tid == 0 && t > 0 && (t & (PUB - 1)) == 0) {
            __threadfence();
            st_release(myflag, t);
        }

        // ======== Stage A: 8 sub-chunks, per-thread cp.async double buffer ========
        {
            ull ar[BG], az[BG], ax[BG];
            #pragma unroll
            for (int b = 0; b < BG; ++b) { ar[b] = 0ull; az[b] = 0ull; ax[b] = 0ull; }

            #pragma unroll
            for (int c = 0; c < NASUB; ++c) {
                CP_WAIT1();            // sub c landed (<=1 newer group pending)
                const uint32_t base = wbuf_s + (uint32_t)((c & 1) * 10 * 64) * 8u;
                #pragma unroll
                for (int kk = 0; kk < 2; ++kk) {
                    const int k = k0 + c * 2 + kk;
                    const ull w1 = *reinterpret_cast<const ull*>(
                        smem_raw + 0) , wdummy = 0; (void)wdummy;
                    ull v1, v2, v3, v4, v5;
                    v1 = sm.wbuf[ks][c & 1][0][kk][jp];
                    v2 = sm.wbuf[ks][c & 1][1][kk][jp];
                    v3 = sm.wbuf[ks][c & 1][2][kk][jp];
                    v4 = sm.wbuf[ks][c & 1][3][kk][jp];
                    v5 = sm.wbuf[ks][c & 1][4][kk][jp];
                    (void)w1; (void)base;
                    #pragma unroll
                    for (int b = 0; b < BG; ++b) {
                        const ulonglong2 hxv = sm.hx[b][k];   // LDS.128 broadcast
                        fma2(ar[b], v1, hxv.x);
                        fma2(ar[b], v2, hxv.y);
                        fma2(az[b], v3, hxv.x);
                        fma2(az[b], v4, hxv.y);
                        fma2(ax[b], v5, hxv.y);
                    }
                }
                if (c <= 5)       issueA(c + 2);
                else if (c == 6)  issueB(0);
                else              issueB(1);
            }
            #pragma unroll
            for (int b = 0; b < BG; ++b) {
                *reinterpret_cast<ull*>(&sm.partA[ks][0][b][j0]) = ar[b];
                *reinterpret_cast<ull*>(&sm.partA[ks][1][b][j0]) = az[b];
                *reinterpret_cast<ull*>(&sm.partA[ks][2][b][j0]) = ax[b];
            }
        }
        __syncthreads();

        // ---- Combine A ----
        for (int i = tid; i < 3 * BG * H; i += NTH) {
            const int g3 = i / (BG * H);
            const int r  = i % (BG * H);
            const int b  = r >> 7;
            const int j  = r & 127;
            float ssum = 0.f;
            #pragma unroll
            for (int ss = 0; ss < KS; ++ss) ssum += sm.partA[ss][g3][b][j];
            if (g3 == 0) {
                const float R  = fast_sigmoid(ssum + sm.br[j]);
                const float rv = R * lo_of(sm.hx[b][j].x);
                sm.rh2[b][j] = pack2(rv, rv);
            } else if (g3 == 1) {
                sm.zbuf[b][j] = fast_sigmoid(ssum + sm.bz[j]);
            } else {
                sm.preh[b][j] = ssum + sm.bh_[j];
            }
        }
        __syncthreads();

        // ======== Stage B: 2 sub-chunks (aliasing A slots), then prefetch next step ========
        {
            ull bh[BG];
            #pragma unroll
            for (int b = 0; b < BG; ++b) bh[b] = 0ull;

            const ull (*wb)[2][5][2][64] = &sm.wbuf[ks];
            #pragma unroll
            for (int d = 0; d < NBSUB; ++d) {
                CP_WAIT1();            // B-sub d landed
                const ull* cells = &(*wb)[d][0][0][0];   // [kk*64 + jp]
                #pragma unroll
                for (int kk = 0; kk < 8; ++kk) {
                    const int k = k0 + d * 8 + kk;
                    const ull w = cells[kk * 64 + jp];
                    #pragma unroll
                    for (int b = 0; b < BG; ++b)
                        fma2(bh[b], w, sm.rh2[b][k]);
                }
                issueA(d);             // next step's A-sub d into slot d
            }
            #pragma unroll
            for (int b = 0; b < BG; ++b)
                *reinterpret_cast<ull*>(&partB[((ks * BG + b) << 7) + j0]) = bh[b];
        }
        __syncthreads();

        // ---- Combine B ----
        for (int i = tid; i < BG * H; i += NTH) {
            const int b = i >> 7;
            const int j = i & 127;
            float ssum = 0.f;
            #pragma unroll
            for (int ss = 0; ss < KS; ++ss) ssum += partB[((ss * BG + b) << 7) + j];
            const float htld = tanhf(ssum + sm.preh[b][j]);
            const float Z    = sm.zbuf[b][j];
            const float hv   = lo_of(sm.hx[b][j].x);
            const float hn   = Z * htld + (1.0f - Z) * hv;
            sm.hx[b][j].x = pack2(hn, hn);
            const int row = row0 + b;
            if (l == LAYERS - 1) {
                if (row < BATCH)
                    out[((size_t)row * T + t) * H + j] = hn;
            } else {
                ysnk[((size_t)t * BPAD + row) * H + j] = hn;
            }
        }
        __syncthreads();
    }

    if (l < LAYERS - 1 && tid == 0) {
        __threadfence();
        st_release(myflag, T);
    }
}

extern "C" void kernel_launch(void* const* d_in, const int* in_sizes, int n_in,
                              void* d_out, int out_size) {
    (void)in_sizes; (void)n_in; (void)out_size;
    const float* inp  = (const float*)d_in[0];
    const float* W_hr = (const float*)d_in[1];
    const float* W_xr = (const float*)d_in[2];
    const float* b_r  = (const float*)d_in[3];
    const float* W_hz = (const float*)d_in[4];
    const float* W_xz = (const float*)d_in[5];
    const float* b_z  = (const float*)d_in[6];
    const float* W_hh = (const float*)d_in[7];
    const float* W_xh = (const float*)d_in[8];
    const float* b_h  = (const float*)d_in[9];
    float* out = (float*)d_out;

    reset_kernel<<<1, 256>>>();

    cudaFuncSetAttribute(gru_layer_kernel,
                         cudaFuncAttributeMaxDynamicSharedMemorySize,
                         (int)sizeof(Smem));
    gru_layer_kernel<<<LAYERS * G, NTH, sizeof(Smem)>>>(
        inp, W_hr, W_xr, b_r, W_hz, W_xz, b_z, W_hh, W_xh, b_h, out);
}

// round 17
// speedup vs baseline: 2.4001x; 1.1153x over previous
#include <cuda_runtime.h>
#include <cstddef>
#include <cstdint>

#define LAYERS 5
#define H 128
#define T 2048
#define BATCH 256
#define G 29           // batch groups per layer (grid = 145)
#define BG 9           // rows per group
#define BPAD 264       // padded batch rows in staging buffer
#define NTH 512
#define KS 8           // k-slices
#define KPER 16        // k rows per slice
#define CHUNK 8        // flag publish granularity

typedef unsigned long long ull;

// Inter-layer staging: Xbuf[l][t][row][j] holds output of layer l (l=0..3)
__device__ float Xbuf[(size_t)(LAYERS - 1) * T * BPAD * H];
__device__ int progressFlag[LAYERS * G];

__device__ __forceinline__ ull pack2(float lo, float hi) {
    ull r; asm("mov.b64 %0,{%1,%2};" : "=l"(r) : "f"(lo), "f"(hi)); return r;
}
__device__ __forceinline__ void fma2(ull& acc, ull a, ull b) {
    asm("fma.rn.f32x2 %0,%1,%2,%0;" : "+l"(acc) : "l"(a), "l"(b));
}
__device__ __forceinline__ float lo_of(ull v) {
    return __uint_as_float((unsigned)(v & 0xffffffffull));
}
__device__ __forceinline__ float fast_sigmoid(float x) {
    return 1.0f / (1.0f + __expf(-x));
}
__device__ __forceinline__ int ld_acquire(const int* p) {
    int v; asm volatile("ld.acquire.gpu.s32 %0,[%1];" : "=r"(v) : "l"(p) : "memory"); return v;
}
__device__ __forceinline__ void st_release(int* p, int v) {
    asm volatile("st.release.gpu.s32 [%0],%1;" :: "l"(p), "r"(v) : "memory");
}

struct Smem {
    float partA[KS][3][BG][H];   // 110592 B  (partB aliases this region)
    float whh_s[H][H];           //  65536 B  resident W_hh (loaded once)
    ull   h2[BG][H];             //   9216 B  (h replicated as f32x2)
    ull   x2[BG][H];             //   9216 B
    ull   rh2[BG][H];            //   9216 B  (R*h replicated)
    float zbuf[BG][H];           //   4608 B
    float preh[BG][H];           //   4608 B
    float br[H];                 //    512 B
    float bz[H];
    float bh_[H];
    int   avail_sh;
};                               // ~214.5 KB
static_assert(sizeof(Smem) <= 232448, "smem over limit");

__global__ void reset_kernel() {
    int i = threadIdx.x;
    if (i < LAYERS * G) progressFlag[i] = 0;
}

__global__ __launch_bounds__(NTH, 1)
void gru_layer_kernel(
    const float* __restrict__ inp,
    const float* __restrict__ W_hr, const float* __restrict__ W_xr, const float* __restrict__ b_r,
    const float* __restrict__ W_hz, const float* __restrict__ W_xz, const float* __restrict__ b_z,
    const float* __restrict__ W_hh, const float* __restrict__ W_xh, const float* __restrict__ b_h,
    float* __restrict__ out)
{
    extern __shared__ char smem_raw[];
    Smem& sm = *reinterpret_cast<Smem*>(smem_raw);
    float* partB = &sm.partA[0][0][0][0];   // [KS][BG][H] alias, disjoint lifetime

    const int bid  = blockIdx.x;
    const int l    = bid / G;          // my layer
    const int g    = bid % G;          // my batch group
    const int row0 = g * BG;
    const int tid  = threadIdx.x;
    const int jp   = tid & 63;         // column pair
    const int j0   = jp << 1;
    const int ks   = tid >> 6;         // k-slice 0..7
    const int k0   = ks * KPER;

    const float* whr = W_hr + l * H * H;
    const float* wxr = W_xr + l * H * H;
    const float* whz = W_hz + l * H * H;
    const float* wxz = W_xz + l * H * H;
    const float* wxh = W_xh + l * H * H;
    const float* whh = W_hh + l * H * H;

    // init: h=0, biases to smem, W_hh resident
    for (int i = tid; i < BG * H; i += NTH)
        sm.h2[0][i] = 0ull;
    for (int i = tid; i < H; i += NTH) {
        sm.br[i]  = b_r[l * H + i];
        sm.bz[i]  = b_z[l * H + i];
        sm.bh_[i] = b_h[l * H + i];
    }
    for (int i = tid; i < H * H / 4; i += NTH)
        reinterpret_cast<float4*>(&sm.whh_s[0][0])[i] =
            reinterpret_cast<const float4*>(whh)[i];
    __syncthreads();

    int avail = (l == 0) ? T : 0;
    const float* xsrc = (l == 0) ? nullptr : &Xbuf[(size_t)(l - 1) * T * BPAD * H];
    float* ysnk = (l == LAYERS - 1) ? nullptr : &Xbuf[(size_t)l * T * BPAD * H];
    int* myflag  = &progressFlag[l * G + g];
    int* srcflag = (l == 0) ? nullptr : &progressFlag[(l - 1) * G + g];

    for (int t = 0; t < T; ++t) {
        // ---- wait for producer (chunked) ----
        if (t >= avail) {
            if (tid == 0) {
                const int need = t + 1;
                int v = ld_acquire(srcflag);
                while (v < need) { __nanosleep(200); v = ld_acquire(srcflag); }
                sm.avail_sh = v;
            }
            __syncthreads();
            avail = sm.avail_sh;
        }

        // ---- load x_t into smem as replicated f32x2 ----
        for (int i = tid; i < BG * H; i += NTH) {
            const int b = i >> 7, k = i & 127;
            const int row = row0 + b;
            float v;
            if (l == 0) {
                v = (row < BATCH) ? inp[((size_t)row * T + t) * H + k] : 0.0f;
            } else {
                v = xsrc[((size_t)t * BPAD + row) * H + k];
            }
            sm.x2[b][k] = pack2(v, v);
        }
        __syncthreads();

        // ======== Stage A: r, z, xh preact partials over my k-slice ========
        {
            ull ar[BG], az[BG], ax[BG];
            #pragma unroll
            for (int b = 0; b < BG; ++b) { ar[b] = 0ull; az[b] = 0ull; ax[b] = 0ull; }

            #pragma unroll 2
            for (int kk = 0; kk < KPER; ++kk) {
                const int k = k0 + kk;
                const ull w1 = __ldg(reinterpret_cast<const ull*>(whr + k * H + j0));
                const ull w2 = __ldg(reinterpret_cast<const ull*>(wxr + k * H + j0));
                const ull w3 = __ldg(reinterpret_cast<const ull*>(whz + k * H + j0));
                const ull w4 = __ldg(reinterpret_cast<const ull*>(wxz + k * H + j0));
                const ull w5 = __ldg(reinterpret_cast<const ull*>(wxh + k * H + j0));
                #pragma unroll
                for (int b = 0; b < BG; ++b) {
                    const ull hb = sm.h2[b][k];   // LDS.64 broadcast
                    const ull xb = sm.x2[b][k];
                    fma2(ar[b], w1, hb);
                    fma2(ar[b], w2, xb);
                    fma2(az[b], w3, hb);
                    fma2(az[b], w4, xb);
                    fma2(ax[b], w5, xb);
                }
            }
            #pragma unroll
            for (int b = 0; b < BG; ++b) {
                *reinterpret_cast<ull*>(&sm.partA[ks][0][b][j0]) = ar[b];
                *reinterpret_cast<ull*>(&sm.partA[ks][1][b][j0]) = az[b];
                *reinterpret_cast<ull*>(&sm.partA[ks][2][b][j0]) = ax[b];
            }
        }
        __syncthreads();

        // ---- Combine A: reduce slices, activations ----
        for (int i = tid; i < 3 * BG * H; i += NTH) {
            const int g3 = i / (BG * H);
            const int r  = i % (BG * H);
            const int b  = r >> 7;
            const int j  = r & 127;
            float ssum = 0.f;
            #pragma unroll
            for (int ss = 0; ss < KS; ++ss) ssum += sm.partA[ss][g3][b][j];
            if (g3 == 0) {
                const float R  = fast_sigmoid(ssum + sm.br[j]);
                const float rv = R * lo_of(sm.h2[b][j]);
                sm.rh2[b][j] = pack2(rv, rv);
            } else if (g3 == 1) {
                sm.zbuf[b][j] = fast_sigmoid(ssum + sm.bz[j]);
            } else {
                sm.preh[b][j] = ssum + sm.bh_[j];
            }
        }
        __syncthreads();

        // ======== Stage B: (R*h) @ W_hh partials — weights from resident smem ========
        {
            ull bh[BG];
            #pragma unroll
            for (int b = 0; b < BG; ++b) bh[b] = 0ull;

            #pragma unroll 4
            for (int kk = 0; kk < KPER; ++kk) {
                const int k = k0 + kk;
                const ull w = *reinterpret_cast<const ull*>(&sm.whh_s[k][j0]);  // LDS.64
                #pragma unroll
                for (int b = 0; b < BG; ++b)
                    fma2(bh[b], w, sm.rh2[b][k]);   // LDS.64 broadcast
            }
            #pragma unroll
            for (int b = 0; b < BG; ++b)
                *reinterpret_cast<ull*>(&partB[((ks * BG + b) << 7) + j0]) = bh[b];
        }
        __syncthreads();

        // ---- Combine B: tanh + blend, update h, emit ----
        for (int i = tid; i < BG * H; i += NTH) {
            const int b = i >> 7;
            const int j = i & 127;
            float ssum = 0.f;
            #pragma unroll
            for (int ss = 0; ss < KS; ++ss) ssum += partB[((ss * BG + b) << 7) + j];
            const float htld = tanhf(ssum + sm.preh[b][j]);
            const float Z    = sm.zbuf[b][j];
            const float hv   = lo_of(sm.h2[b][j]);
            const float hn   = Z * htld + (1.0f - Z) * hv;
            sm.h2[b][j] = pack2(hn, hn);
            const int row = row0 + b;
            if (l == LAYERS - 1) {
                if (row < BATCH)
                    out[((size_t)row * T + t) * H + j] = hn;
            } else {
                ysnk[((size_t)t * BPAD + row) * H + j] = hn;
            }
        }
        __syncthreads();

        // ---- publish progress (chunked) ----
        if (l < LAYERS - 1 && tid == 0) {
            const int t1 = t + 1;
            if ((t1 & (CHUNK - 1)) == 0 || t1 == T) {
                __threadfence();
                st_release(myflag, t1);
            }
        }
    }
}

extern "C" void kernel_launch(void* const* d_in, const int* in_sizes, int n_in,
                              void* d_out, int out_size) {
    (void)in_sizes; (void)n_in; (void)out_size;
    const float* inp  = (const float*)d_in[0];
    const float* W_hr = (const float*)d_in[1];
    const float* W_xr = (const float*)d_in[2];
    const float* b_r  = (const float*)d_in[3];
    const float* W_hz = (const float*)d_in[4];
    const float* W_xz = (const float*)d_in[5];
    const float* b_z  = (const float*)d_in[6];
    const float* W_hh = (const float*)d_in[7];
    const float* W_xh = (const float*)d_in[8];
    const float* b_h  = (const float*)d_in[9];
    float* out = (float*)d_out;

    reset_kernel<<<1, 256>>>();

    cudaFuncSetAttribute(gru_layer_kernel,
                         cudaFuncAttributeMaxDynamicSharedMemorySize,
                         (int)sizeof(Smem));
    gru_layer_kernel<<<LAYERS * G, NTH, sizeof(Smem)>>>(
        inp, W_hr, W_xr, b_r, W_hz, W_xz, b_z, W_hh, W_xh, b_h, out);
}